// round 7
// baseline (speedup 1.0000x reference)
#include <cuda_runtime.h>
#include <cuda_bf16.h>
#include <cstdint>

#define GK   192
#define NPIX 65536

// ---------------------------------------------------------------------------
// scratch (allocation-free rule: __device__ globals)
// ---------------------------------------------------------------------------
__device__ float g_qkv[75497472];                         // [2][576][65536] f32
__device__ float g_att[25165824];                         // [2][192][65536] f32
__device__ __align__(16) unsigned short g_bth[25165824];  // [2][65536][192] bf16 hi
__device__ __align__(16) unsigned short g_btl[25165824];  // [2][65536][192] bf16 lo
__device__ __align__(16) unsigned short g_wqh[110592], g_wql[110592];
__device__ __align__(16) unsigned short g_wph[36864],  g_wpl[36864];

// ---------------------------------------------------------------------------
__device__ __forceinline__ uint32_t smem_u32(const void* p) {
    uint32_t a;
    asm("{ .reg .u64 t; cvta.to.shared.u64 t, %1; cvt.u32.u64 %0, t; }"
        : "=r"(a) : "l"(p));
    return a;
}

__device__ __forceinline__ void cp_async16(uint32_t dst, const void* src) {
    asm volatile("cp.async.cg.shared.global [%0], [%1], 16;"
                 :: "r"(dst), "l"(src) : "memory");
}

#define LDSM_X4(r0, r1, r2, r3, a) \
    asm volatile("ldmatrix.sync.aligned.m8n8.x4.shared.b16 {%0,%1,%2,%3}, [%4];" \
                 : "=r"(r0), "=r"(r1), "=r"(r2), "=r"(r3) : "r"(a))

#define MMA16816(d, a, b) \
    asm volatile("mma.sync.aligned.m16n8k16.row.col.f32.bf16.bf16.f32 " \
                 "{%0,%1,%2,%3}, {%4,%5,%6,%7}, {%8,%9}, {%0,%1,%2,%3};" \
                 : "+f"((d)[0]), "+f"((d)[1]), "+f"((d)[2]), "+f"((d)[3]) \
                 : "r"((a)[0]), "r"((a)[1]), "r"((a)[2]), "r"((a)[3]), \
                   "r"((b)[0]), "r"((b)[1]))

// packed fp32x2 FMA + broadcast-pack (Blackwell)
#define FMA2(d, a, b) \
    asm("fma.rn.f32x2 %0, %1, %2, %3;" : "=l"(d) : "l"(a), "l"(b), "l"(d))
#define PACK2(d, s) \
    asm("mov.b64 %0, {%1, %1};" : "=l"(d) : "f"(s))

// ---------------------------------------------------------------------------
// convert + transpose: src f32 [2][192][65536] -> dhi/dlo bf16 [2][65536][192]
// ---------------------------------------------------------------------------
__global__ __launch_bounds__(256) void convtrans(
    const float* __restrict__ src,
    unsigned short* __restrict__ dhi,
    unsigned short* __restrict__ dlo)
{
    __shared__ float sm[32][33];
    const int p0 = blockIdx.x * 32, c0 = blockIdx.y * 32, b = blockIdx.z;
    const float* s = src + (size_t)b * GK * NPIX;
    const int tc = threadIdx.x & 31, tr = threadIdx.x >> 5;

    #pragma unroll
    for (int i = 0; i < 4; i++) {
        int cl = tr + i * 8;
        sm[cl][tc] = s[(size_t)(c0 + cl) * NPIX + p0 + tc];
    }
    __syncthreads();

    const size_t obase = (size_t)b * NPIX * GK;
    #pragma unroll
    for (int i = 0; i < 4; i++) {
        int pl = tr + i * 8;
        float v = sm[tc][pl];
        __nv_bfloat16 h = __float2bfloat16(v);
        __nv_bfloat16 l = __float2bfloat16(v - __bfloat162float(h));
        size_t o = obase + (size_t)(p0 + pl) * GK + c0 + tc;
        dhi[o] = *(unsigned short*)&h;
        dlo[o] = *(unsigned short*)&l;
    }
}

__global__ void wconvert(const float* __restrict__ w, int n,
                         unsigned short* __restrict__ hi,
                         unsigned short* __restrict__ lo)
{
    int i = blockIdx.x * 256 + threadIdx.x;
    if (i < n) {
        float v = w[i];
        __nv_bfloat16 h = __float2bfloat16(v);
        __nv_bfloat16 l = __float2bfloat16(v - __bfloat162float(h));
        hi[i] = *(unsigned short*)&h;
        lo[i] = *(unsigned short*)&l;
    }
}

// ---------------------------------------------------------------------------
// mma.sync GEMM:  C[b,m,n] = sum_k A[m,k] * B[b,n,k]   (3-term bf16 split)
// CTA 64(M) x 128(N), 8 warps (2Mx4N), warp 32x32 via 2x4 m16n8k16 tiles.
// K=192 in four 48-chunks, cp.async double-buffered. B frags via ldmatrix.x4
// pairs (8 ldmatrix / k-step instead of 12). Row pitch 56 bf16: conflict-free.
// ---------------------------------------------------------------------------
__global__ __launch_bounds__(256) void gemm_mma(
    const unsigned short* __restrict__ Ahi,
    const unsigned short* __restrict__ Alo,
    const unsigned short* __restrict__ Bhi,
    const unsigned short* __restrict__ Blo,
    float* __restrict__ Cm, int Mtot)
{
    extern __shared__ __align__(16) unsigned short smem[];
    const int t = threadIdx.x, lane = t & 31, w = t >> 5;
    const int bM = blockIdx.x * 64;
    const size_t bN = (size_t)blockIdx.y * 128;
    const int batch = blockIdx.z;
    const int wm0 = (w >> 2) * 32;
    const int wn0 = (w & 3) * 32;

    const uint32_t sb = smem_u32(smem);
    // per buffer (43008 B): A [hl][64][56] at 0, B [hl][128][56] at elem 7168

    const unsigned short* gA[2] = { Ahi + (size_t)bM * GK, Alo + (size_t)bM * GK };
    const size_t boff = ((size_t)batch * NPIX + bN) * GK;
    const unsigned short* gB[2] = { Bhi + boff, Blo + boff };

    auto issue_chunk = [&](int c) {
        const uint32_t sbase = sb + (uint32_t)(c & 1) * 43008u;
        #pragma unroll
        for (int i = 0; i < 3; i++) {
            int id = t + i * 256;
            int hl = id / 384, rem = id - hl * 384;
            int row = rem / 6, c6 = rem - row * 6;
            uint32_t d = sbase + (uint32_t)(hl * 3584 + row * 56 + c6 * 8) * 2u;
            cp_async16(d, gA[hl] + row * GK + c * 48 + c6 * 8);
        }
        #pragma unroll
        for (int i = 0; i < 6; i++) {
            int id = t + i * 256;
            int hl = id / 768, rem = id - hl * 768;
            int row = rem / 6, c6 = rem - row * 6;
            uint32_t d = sbase + (uint32_t)(7168 + hl * 7168 + row * 56 + c6 * 8) * 2u;
            cp_async16(d, gB[hl] + row * GK + c * 48 + c6 * 8);
        }
        asm volatile("cp.async.commit_group;" ::: "memory");
    };

    float acc[2][4][4];
    #pragma unroll
    for (int mi = 0; mi < 2; mi++)
        #pragma unroll
        for (int ni = 0; ni < 4; ni++)
            #pragma unroll
            for (int r = 0; r < 4; r++) acc[mi][ni][r] = 0.f;

    const int arow  = lane & 15;
    const int akoff = (lane >> 4) * 8;
    const int bg    = lane >> 3;          // 0..3 lane-group for B x4
    const int brow8 = lane & 7;

    issue_chunk(0);
    #pragma unroll 1
    for (int c = 0; c < 4; c++) {
        if (c + 1 < 4) {
            issue_chunk(c + 1);
            asm volatile("cp.async.wait_group 1;" ::: "memory");
        } else {
            asm volatile("cp.async.wait_group 0;" ::: "memory");
        }
        __syncthreads();

        const uint32_t sbase = sb + (uint32_t)(c & 1) * 43008u;
        #pragma unroll
        for (int ks = 0; ks < 3; ks++) {
            const int k0 = ks * 16;
            uint32_t ah[2][4], al[2][4], bh[4][2], bl[4][2];
            #pragma unroll
            for (int mi = 0; mi < 2; mi++) {
                uint32_t off = (uint32_t)((wm0 + mi * 16 + arow) * 56 + k0 + akoff) * 2u;
                LDSM_X4(ah[mi][0], ah[mi][1], ah[mi][2], ah[mi][3], sbase + off);
                LDSM_X4(al[mi][0], al[mi][1], al[mi][2], al[mi][3],
                        sbase + 3584u * 2u + off);
            }
            // B: one x4 per (hl, n-pair): lane groups map to (n, k-half)
            #pragma unroll
            for (int np = 0; np < 2; np++) {
                uint32_t off = (uint32_t)(7168
                    + (wn0 + (2 * np + (bg >> 1)) * 8 + brow8) * 56
                    + k0 + (bg & 1) * 8) * 2u;
                LDSM_X4(bh[2*np][0], bh[2*np][1], bh[2*np+1][0], bh[2*np+1][1],
                        sbase + off);
                LDSM_X4(bl[2*np][0], bl[2*np][1], bl[2*np+1][0], bl[2*np+1][1],
                        sbase + 7168u * 2u + off);
            }
            #pragma unroll
            for (int mi = 0; mi < 2; mi++)
                #pragma unroll
                for (int ni = 0; ni < 4; ni++) {
                    MMA16816(acc[mi][ni], ah[mi], bh[ni]);
                    MMA16816(acc[mi][ni], ah[mi], bl[ni]);
                    MMA16816(acc[mi][ni], al[mi], bh[ni]);
                }
        }
        __syncthreads();
    }

    float* C = Cm + (size_t)batch * (size_t)Mtot * NPIX;
    const int mr = lane >> 2, nc = (lane & 3) * 2;
    #pragma unroll
    for (int mi = 0; mi < 2; mi++)
        #pragma unroll
        for (int ni = 0; ni < 4; ni++) {
            const size_t m = (size_t)(bM + wm0 + mi * 16 + mr);
            const size_t n = bN + wn0 + ni * 8 + nc;
            float* a = acc[mi][ni];
            *(float2*)&C[m * NPIX + n]       = make_float2(a[0], a[1]);
            *(float2*)&C[(m + 8) * NPIX + n] = make_float2(a[2], a[3]);
        }
}

// ---------------------------------------------------------------------------
// Fused depthwise-3x3 + 8x8-window channel attention, f32x2-packed math.
// One CTA per (window, head): 8192 CTAs, 256 threads.
// Layouts: sq/sv [48][68] (pitch 68: aligned + conflict-free LDS.128),
//          skT [64][52], sattn [48][52].
// ---------------------------------------------------------------------------
__global__ __launch_bounds__(256) void window_attn(
    const float* __restrict__ dww,    // [576*9]
    const float* __restrict__ tempr)  // [4]
{
    const int t    = threadIdx.x;
    const int head = blockIdx.x & 3;
    const int win  = blockIdx.x >> 2;
    const int b    = win >> 10;
    const int hn   = (win >> 5) & 31;
    const int wn   = win & 31;
    const int y0   = hn << 3, x0 = wn << 3;

    __shared__ __align__(16) float sq[48 * 68];
    __shared__ __align__(16) float skT[64 * 52];
    __shared__ __align__(16) float sv[48 * 68];
    __shared__ __align__(16) float uni[2496];   // halo [24][100] -> attn [48][52]
    __shared__ float qin[48], kin[48];

    const size_t qkv_base = (size_t)b * 576 * NPIX;

    float hreg[10];
    auto load_halo = [&](int gch0) {
        #pragma unroll
        for (int i = 0; i < 10; i++) {
            int e = t + i * 256;
            float v = 0.f;
            if (e < 2400) {
                int c  = e / 100;
                int px = e - c * 100;
                int iy = px / 10;
                int ix = px - iy * 10;
                int gy = y0 - 1 + iy;
                int gx = x0 - 1 + ix;
                if ((unsigned)gy < 256u && (unsigned)gx < 256u)
                    v = g_qkv[qkv_base + (size_t)(gch0 + c) * NPIX + gy * 256 + gx];
            }
            hreg[i] = v;
        }
    };

    load_halo(head * 48);
    #pragma unroll 1
    for (int p = 0; p < 6; p++) {
        const int tensor = p >> 1;
        const int half   = p & 1;
        const int gch0   = tensor * 192 + head * 48 + half * 24;

        #pragma unroll
        for (int i = 0; i < 10; i++) {
            int e = t + i * 256;
            if (e < 2400) uni[e] = hreg[i];
        }
        __syncthreads();

        if (p < 5) {
            const int np = p + 1;
            load_halo((np >> 1) * 192 + head * 48 + (np & 1) * 24);
        }

        #pragma unroll
        for (int u = 0; u < 6; u++) {
            int e  = t + u * 256;
            int c  = e >> 6;
            int pp = e & 63;
            int p1 = pp >> 3, p2 = pp & 7;
            const float* wr = dww + (gch0 + c) * 9;
            const float* tp = uni + c * 100 + p1 * 10 + p2;
            float s = tp[ 0]*wr[0] + tp[ 1]*wr[1] + tp[ 2]*wr[2]
                    + tp[10]*wr[3] + tp[11]*wr[4] + tp[12]*wr[5]
                    + tp[20]*wr[6] + tp[21]*wr[7] + tp[22]*wr[8];
            int ch = half * 24 + c;
            if      (tensor == 0) sq[ch * 68 + pp]  = s;
            else if (tensor == 1) skT[pp * 52 + ch] = s;
            else                  sv[ch * 68 + pp]  = s;
        }
        __syncthreads();
    }

    // ---- l2 norms ----
    if (t < 48) {
        float s = 0.f;
        #pragma unroll 8
        for (int d = 0; d < 64; d++) {
            float x = sq[t * 68 + ((d + t) & 63)];
            s = fmaf(x, x, s);
        }
        qin[t] = 1.f / fmaxf(sqrtf(s), 1e-12f);
    } else if (t >= 128 && t < 176) {
        int j = t - 128;
        float s = 0.f;
        #pragma unroll 8
        for (int d = 0; d < 64; d++) {
            float x = skT[d * 52 + j];
            s = fmaf(x, x, s);
        }
        kin[j] = 1.f / fmaxf(sqrtf(s), 1e-12f);
    }
    __syncthreads();

    float* sattn = uni;                            // [48][52]
    const float tscale = __ldg(&tempr[head]);

    // ---- logits: 3i x 4j tile in f32x2 (192 active threads) ----
    {
        const int ti = t >> 4;            // 0..15 -> i0 = 3*ti
        const int tj = t & 15;            // 0..11 active -> j0 = 4*tj
        if (tj < 12) {
            const int i0 = ti * 3, j0 = tj * 4;
            unsigned long long acc2[3][2] = {{0ull,0ull},{0ull,0ull},{0ull,0ull}};
            #pragma unroll 4
            for (int d0 = 0; d0 < 64; d0 += 4) {
                float4 qv[3];
                unsigned long long q2[3][4];
                #pragma unroll
                for (int r = 0; r < 3; r++) {
                    qv[r] = *(const float4*)&sq[(i0 + r) * 68 + d0];
                    PACK2(q2[r][0], qv[r].x); PACK2(q2[r][1], qv[r].y);
                    PACK2(q2[r][2], qv[r].z); PACK2(q2[r][3], qv[r].w);
                }
                #pragma unroll
                for (int dd = 0; dd < 4; dd++) {
                    ulonglong2 kk = *(const ulonglong2*)&skT[(d0 + dd) * 52 + j0];
                    #pragma unroll
                    for (int r = 0; r < 3; r++) {
                        FMA2(acc2[r][0], q2[r][dd], kk.x);
                        FMA2(acc2[r][1], q2[r][dd], kk.y);
                    }
                }
            }
            float k0s = kin[j0], k1s = kin[j0+1], k2s = kin[j0+2], k3s = kin[j0+3];
            #pragma unroll
            for (int r = 0; r < 3; r++) {
                float qi = qin[i0 + r] * tscale;
                float2 p0 = *(float2*)&acc2[r][0];
                float2 p1 = *(float2*)&acc2[r][1];
                *(float4*)&sattn[(i0 + r) * 52 + j0] = make_float4(
                    p0.x * qi * k0s, p0.y * qi * k1s,
                    p1.x * qi * k2s, p1.y * qi * k3s);
            }
        }
    }
    __syncthreads();

    // ---- softmax over j ----
    if (t < 48) {
        float m = -1e30f;
        #pragma unroll 8
        for (int j = 0; j < 48; j++) m = fmaxf(m, sattn[t * 52 + j]);
        float s = 0.f;
        #pragma unroll 8
        for (int j = 0; j < 48; j++) {
            float e = __expf(sattn[t * 52 + j] - m);
            sattn[t * 52 + j] = e;
            s += e;
        }
        float inv = 1.f / s;
        #pragma unroll 8
        for (int j = 0; j < 48; j++) sattn[t * 52 + j] *= inv;
    }
    __syncthreads();

    // ---- out = attn @ v ; 3i x 4d tile in f32x2 ----
    {
        const int td = t & 15;            // d0 = 4*td
        const int ti = t >> 4;            // i0 = 3*ti
        const int d0 = td * 4, i0 = ti * 3;
        unsigned long long acc2[3][2] = {{0ull,0ull},{0ull,0ull},{0ull,0ull}};
        #pragma unroll 4
        for (int j = 0; j < 48; j++) {
            ulonglong2 vv = *(const ulonglong2*)&sv[j * 68 + d0];
            #pragma unroll
            for (int r = 0; r < 3; r++) {
                unsigned long long a2;
                PACK2(a2, sattn[(i0 + r) * 52 + j]);
                FMA2(acc2[r][0], a2, vv.x);
                FMA2(acc2[r][1], a2, vv.y);
            }
        }
        const int p1 = d0 >> 3, p2 = d0 & 7;
        const size_t obase = (size_t)b * 192 * NPIX
                           + (size_t)(y0 + p1) * 256 + (x0 + p2);
        #pragma unroll
        for (int r = 0; r < 3; r++) {
            size_t off = obase + (size_t)(head * 48 + i0 + r) * NPIX;
            float2 f0 = *(float2*)&acc2[r][0];
            float2 f1 = *(float2*)&acc2[r][1];
            *(float4*)&g_att[off] = make_float4(f0.x, f0.y, f1.x, f1.y);
        }
    }
}

// ---------------------------------------------------------------------------
extern "C" void kernel_launch(void* const* d_in, const int* in_sizes, int n_in,
                              void* d_out, int out_size)
{
    const float *x = nullptr, *qw = nullptr, *dw = nullptr, *pw = nullptr, *tp = nullptr;
    for (int i = 0; i < n_in; i++) {
        switch (in_sizes[i]) {
            case 25165824: x  = (const float*)d_in[i]; break;  // x [2,192,256,256]
            case 110592:   qw = (const float*)d_in[i]; break;  // qkv_w [576,192]
            case 5184:     dw = (const float*)d_in[i]; break;  // dw_w [576,1,3,3]
            case 36864:    pw = (const float*)d_in[i]; break;  // proj_w [192,192]
            case 4:        tp = (const float*)d_in[i]; break;  // temperature [4]
        }
    }

    void *qkvp, *attp, *bthp, *btlp, *wqhp, *wqlp, *wphp, *wplp;
    cudaGetSymbolAddress(&qkvp, g_qkv);
    cudaGetSymbolAddress(&attp, g_att);
    cudaGetSymbolAddress(&bthp, g_bth);
    cudaGetSymbolAddress(&btlp, g_btl);
    cudaGetSymbolAddress(&wqhp, g_wqh);
    cudaGetSymbolAddress(&wqlp, g_wql);
    cudaGetSymbolAddress(&wphp, g_wph);
    cudaGetSymbolAddress(&wplp, g_wpl);

    const int GEMM_SMEM = 2 * 43008;             // 86016 B
    cudaFuncSetAttribute(gemm_mma, cudaFuncAttributeMaxDynamicSharedMemorySize, GEMM_SMEM);

    wconvert<<<(110592 + 255) / 256, 256>>>(qw, 110592,
        (unsigned short*)wqhp, (unsigned short*)wqlp);
    wconvert<<<(36864 + 255) / 256, 256>>>(pw, 36864,
        (unsigned short*)wphp, (unsigned short*)wplp);

    convtrans<<<dim3(2048, 6, 2), 256>>>(x,
        (unsigned short*)bthp, (unsigned short*)btlp);

    gemm_mma<<<dim3(9, 512, 2), 256, GEMM_SMEM>>>(
        (const unsigned short*)wqhp, (const unsigned short*)wqlp,
        (const unsigned short*)bthp, (const unsigned short*)btlp,
        (float*)qkvp, 576);

    window_attn<<<8192, 256>>>(dw, tp);

    convtrans<<<dim3(2048, 6, 2), 256>>>((const float*)attp,
        (unsigned short*)bthp, (unsigned short*)btlp);

    gemm_mma<<<dim3(3, 512, 2), 256, GEMM_SMEM>>>(
        (const unsigned short*)wphp, (const unsigned short*)wplp,
        (const unsigned short*)bthp, (const unsigned short*)btlp,
        (float*)d_out, 192);
}

// round 8
// speedup vs baseline: 1.0533x; 1.0533x over previous
#include <cuda_runtime.h>
#include <cuda_bf16.h>
#include <cstdint>

#define GK   192
#define NPIX 65536

// ---------------------------------------------------------------------------
// scratch (allocation-free rule: __device__ globals)
// ---------------------------------------------------------------------------
__device__ float g_qkv[75497472];                         // [2][576][65536] f32
__device__ __align__(16) unsigned short g_bth[25165824];  // [2][65536][192] bf16 hi
__device__ __align__(16) unsigned short g_btl[25165824];  // [2][65536][192] bf16 lo
__device__ __align__(16) unsigned short g_wqh[110592], g_wql[110592];
__device__ __align__(16) unsigned short g_wph[36864],  g_wpl[36864];

// ---------------------------------------------------------------------------
__device__ __forceinline__ uint32_t smem_u32(const void* p) {
    uint32_t a;
    asm("{ .reg .u64 t; cvta.to.shared.u64 t, %1; cvt.u32.u64 %0, t; }"
        : "=r"(a) : "l"(p));
    return a;
}

__device__ __forceinline__ void cp_async16(uint32_t dst, const void* src) {
    asm volatile("cp.async.cg.shared.global [%0], [%1], 16;"
                 :: "r"(dst), "l"(src) : "memory");
}

#define LDSM_X4(r0, r1, r2, r3, a) \
    asm volatile("ldmatrix.sync.aligned.m8n8.x4.shared.b16 {%0,%1,%2,%3}, [%4];" \
                 : "=r"(r0), "=r"(r1), "=r"(r2), "=r"(r3) : "r"(a))

#define MMA16816(d, a, b) \
    asm volatile("mma.sync.aligned.m16n8k16.row.col.f32.bf16.bf16.f32 " \
                 "{%0,%1,%2,%3}, {%4,%5,%6,%7}, {%8,%9}, {%0,%1,%2,%3};" \
                 : "+f"((d)[0]), "+f"((d)[1]), "+f"((d)[2]), "+f"((d)[3]) \
                 : "r"((a)[0]), "r"((a)[1]), "r"((a)[2]), "r"((a)[3]), \
                   "r"((b)[0]), "r"((b)[1]))

// ---------------------------------------------------------------------------
// convert + transpose: src f32 [2][192][65536] -> dhi/dlo bf16 [2][65536][192]
// ---------------------------------------------------------------------------
__global__ __launch_bounds__(256) void convtrans(
    const float* __restrict__ src,
    unsigned short* __restrict__ dhi,
    unsigned short* __restrict__ dlo)
{
    __shared__ float sm[32][33];
    const int p0 = blockIdx.x * 32, c0 = blockIdx.y * 32, b = blockIdx.z;
    const float* s = src + (size_t)b * GK * NPIX;
    const int tc = threadIdx.x & 31, tr = threadIdx.x >> 5;

    #pragma unroll
    for (int i = 0; i < 4; i++) {
        int cl = tr + i * 8;
        sm[cl][tc] = s[(size_t)(c0 + cl) * NPIX + p0 + tc];
    }
    __syncthreads();

    const size_t obase = (size_t)b * NPIX * GK;
    #pragma unroll
    for (int i = 0; i < 4; i++) {
        int pl = tr + i * 8;
        float v = sm[tc][pl];
        __nv_bfloat16 h = __float2bfloat16(v);
        __nv_bfloat16 l = __float2bfloat16(v - __bfloat162float(h));
        size_t o = obase + (size_t)(p0 + pl) * GK + c0 + tc;
        dhi[o] = *(unsigned short*)&h;
        dlo[o] = *(unsigned short*)&l;
    }
}

__global__ void wconvert(const float* __restrict__ w, int n,
                         unsigned short* __restrict__ hi,
                         unsigned short* __restrict__ lo)
{
    int i = blockIdx.x * 256 + threadIdx.x;
    if (i < n) {
        float v = w[i];
        __nv_bfloat16 h = __float2bfloat16(v);
        __nv_bfloat16 l = __float2bfloat16(v - __bfloat162float(h));
        hi[i] = *(unsigned short*)&h;
        lo[i] = *(unsigned short*)&l;
    }
}

// ---------------------------------------------------------------------------
// mma.sync GEMM:  C[b,m,n] = sum_k A[m,k] * B[b,n,k]   (3-term bf16 split)
// CTA 64(M) x 128(N), 8 warps (2Mx4N), warp 32x32 via 2x4 m16n8k16 tiles.
// Inner product ordered TERM-OUTER: 8 independent MMAs between accumulator
// reuses (the R7 mi/ni-outer order had 3-deep RAW chains on each acc).
// ---------------------------------------------------------------------------
__global__ __launch_bounds__(256) void gemm_mma(
    const unsigned short* __restrict__ Ahi,
    const unsigned short* __restrict__ Alo,
    const unsigned short* __restrict__ Bhi,
    const unsigned short* __restrict__ Blo,
    float* __restrict__ Cm, int Mtot)
{
    extern __shared__ __align__(16) unsigned short smem[];
    const int t = threadIdx.x, lane = t & 31, w = t >> 5;
    const int bM = blockIdx.x * 64;
    const size_t bN = (size_t)blockIdx.y * 128;
    const int batch = blockIdx.z;
    const int wm0 = (w >> 2) * 32;
    const int wn0 = (w & 3) * 32;

    const uint32_t sb = smem_u32(smem);
    // per buffer (43008 B): A [hl][64][56] at 0, B [hl][128][56] at elem 7168

    const unsigned short* gA[2] = { Ahi + (size_t)bM * GK, Alo + (size_t)bM * GK };
    const size_t boff = ((size_t)batch * NPIX + bN) * GK;
    const unsigned short* gB[2] = { Bhi + boff, Blo + boff };

    auto issue_chunk = [&](int c) {
        const uint32_t sbase = sb + (uint32_t)(c & 1) * 43008u;
        #pragma unroll
        for (int i = 0; i < 3; i++) {
            int id = t + i * 256;
            int hl = id / 384, rem = id - hl * 384;
            int row = rem / 6, c6 = rem - row * 6;
            uint32_t d = sbase + (uint32_t)(hl * 3584 + row * 56 + c6 * 8) * 2u;
            cp_async16(d, gA[hl] + row * GK + c * 48 + c6 * 8);
        }
        #pragma unroll
        for (int i = 0; i < 6; i++) {
            int id = t + i * 256;
            int hl = id / 768, rem = id - hl * 768;
            int row = rem / 6, c6 = rem - row * 6;
            uint32_t d = sbase + (uint32_t)(7168 + hl * 7168 + row * 56 + c6 * 8) * 2u;
            cp_async16(d, gB[hl] + row * GK + c * 48 + c6 * 8);
        }
        asm volatile("cp.async.commit_group;" ::: "memory");
    };

    float acc[2][4][4];
    #pragma unroll
    for (int mi = 0; mi < 2; mi++)
        #pragma unroll
        for (int ni = 0; ni < 4; ni++)
            #pragma unroll
            for (int r = 0; r < 4; r++) acc[mi][ni][r] = 0.f;

    const int arow  = lane & 15;
    const int akoff = (lane >> 4) * 8;
    const int bg    = lane >> 3;
    const int brow8 = lane & 7;

    issue_chunk(0);
    #pragma unroll 1
    for (int c = 0; c < 4; c++) {
        if (c + 1 < 4) {
            issue_chunk(c + 1);
            asm volatile("cp.async.wait_group 1;" ::: "memory");
        } else {
            asm volatile("cp.async.wait_group 0;" ::: "memory");
        }
        __syncthreads();

        const uint32_t sbase = sb + (uint32_t)(c & 1) * 43008u;
        #pragma unroll
        for (int ks = 0; ks < 3; ks++) {
            const int k0 = ks * 16;
            uint32_t ah[2][4], al[2][4], bh[4][2], bl[4][2];
            #pragma unroll
            for (int mi = 0; mi < 2; mi++) {
                uint32_t off = (uint32_t)((wm0 + mi * 16 + arow) * 56 + k0 + akoff) * 2u;
                LDSM_X4(ah[mi][0], ah[mi][1], ah[mi][2], ah[mi][3], sbase + off);
                LDSM_X4(al[mi][0], al[mi][1], al[mi][2], al[mi][3],
                        sbase + 3584u * 2u + off);
            }
            #pragma unroll
            for (int np = 0; np < 2; np++) {
                uint32_t off = (uint32_t)(7168
                    + (wn0 + (2 * np + (bg >> 1)) * 8 + brow8) * 56
                    + k0 + (bg & 1) * 8) * 2u;
                LDSM_X4(bh[2*np][0], bh[2*np][1], bh[2*np+1][0], bh[2*np+1][1],
                        sbase + off);
                LDSM_X4(bl[2*np][0], bl[2*np][1], bl[2*np+1][0], bl[2*np+1][1],
                        sbase + 7168u * 2u + off);
            }
            // term-outer: 8 independent MMAs between reuses of each acc
            #pragma unroll
            for (int mi = 0; mi < 2; mi++)
                #pragma unroll
                for (int ni = 0; ni < 4; ni++)
                    MMA16816(acc[mi][ni], ah[mi], bh[ni]);
            #pragma unroll
            for (int mi = 0; mi < 2; mi++)
                #pragma unroll
                for (int ni = 0; ni < 4; ni++)
                    MMA16816(acc[mi][ni], ah[mi], bl[ni]);
            #pragma unroll
            for (int mi = 0; mi < 2; mi++)
                #pragma unroll
                for (int ni = 0; ni < 4; ni++)
                    MMA16816(acc[mi][ni], al[mi], bh[ni]);
        }
        __syncthreads();
    }

    float* C = Cm + (size_t)batch * (size_t)Mtot * NPIX;
    const int mr = lane >> 2, nc = (lane & 3) * 2;
    #pragma unroll
    for (int mi = 0; mi < 2; mi++)
        #pragma unroll
        for (int ni = 0; ni < 4; ni++) {
            const size_t m = (size_t)(bM + wm0 + mi * 16 + mr);
            const size_t n = bN + wn0 + ni * 8 + nc;
            float* a = acc[mi][ni];
            *(float2*)&C[m * NPIX + n]       = make_float2(a[0], a[1]);
            *(float2*)&C[(m + 8) * NPIX + n] = make_float2(a[2], a[3]);
        }
}

// ---------------------------------------------------------------------------
// Fused depthwise-3x3 + 8x8-window channel attention (R6-proven core) with a
// fused epilogue: output written directly as transposed bf16 hi/lo
// ([b][pix][192]) for the proj GEMM — eliminates the second convtrans pass.
// ---------------------------------------------------------------------------
__global__ __launch_bounds__(256) void window_attn(
    const float* __restrict__ dww,    // [576*9]
    const float* __restrict__ tempr)  // [4]
{
    const int t    = threadIdx.x;
    const int head = blockIdx.x & 3;
    const int win  = blockIdx.x >> 2;
    const int b    = win >> 10;
    const int hn   = (win >> 5) & 31;
    const int wn   = win & 31;
    const int y0   = hn << 3, x0 = wn << 3;

    __shared__ float sq[48 * 64];
    __shared__ float skT[64 * 52];       // later reused as u32 staging [64][52]
    __shared__ float sv[48 * 64];
    __shared__ float scratch[2400];      // halo [24][100] -> attn [48][49]
    __shared__ float qin[48], kin[48];

    const size_t qkv_base = (size_t)b * 576 * NPIX;

    float hreg[10];
    auto load_halo = [&](int gch0) {
        #pragma unroll
        for (int i = 0; i < 10; i++) {
            int e = t + i * 256;
            float v = 0.f;
            if (e < 2400) {
                int c  = e / 100;
                int px = e - c * 100;
                int iy = px / 10;
                int ix = px - iy * 10;
                int gy = y0 - 1 + iy;
                int gx = x0 - 1 + ix;
                if ((unsigned)gy < 256u && (unsigned)gx < 256u)
                    v = g_qkv[qkv_base + (size_t)(gch0 + c) * NPIX + gy * 256 + gx];
            }
            hreg[i] = v;
        }
    };

    load_halo(head * 48);
    #pragma unroll 1
    for (int p = 0; p < 6; p++) {
        const int tensor = p >> 1;
        const int half   = p & 1;
        const int gch0   = tensor * 192 + head * 48 + half * 24;

        #pragma unroll
        for (int i = 0; i < 10; i++) {
            int e = t + i * 256;
            if (e < 2400) scratch[e] = hreg[i];
        }
        __syncthreads();

        if (p < 5) {
            const int np = p + 1;
            load_halo((np >> 1) * 192 + head * 48 + (np & 1) * 24);
        }

        #pragma unroll
        for (int u = 0; u < 6; u++) {
            int e  = t + u * 256;
            int c  = e >> 6;
            int pp = e & 63;
            int p1 = pp >> 3, p2 = pp & 7;
            const float* wr = dww + (gch0 + c) * 9;
            const float* tp = scratch + c * 100 + p1 * 10 + p2;
            float s = tp[ 0]*wr[0] + tp[ 1]*wr[1] + tp[ 2]*wr[2]
                    + tp[10]*wr[3] + tp[11]*wr[4] + tp[12]*wr[5]
                    + tp[20]*wr[6] + tp[21]*wr[7] + tp[22]*wr[8];
            int ch = half * 24 + c;
            if      (tensor == 0) sq[ch * 64 + pp]  = s;
            else if (tensor == 1) skT[pp * 52 + ch] = s;
            else                  sv[ch * 64 + pp]  = s;
        }
        __syncthreads();
    }

    if (t < 48) {
        float s = 0.f;
        #pragma unroll 8
        for (int d = 0; d < 64; d++) {
            float x = sq[t * 64 + ((d + t) & 63)];
            s = fmaf(x, x, s);
        }
        qin[t] = 1.f / fmaxf(sqrtf(s), 1e-12f);
    } else if (t >= 128 && t < 176) {
        int j = t - 128;
        float s = 0.f;
        #pragma unroll 8
        for (int d = 0; d < 64; d++) {
            float x = skT[d * 52 + j];
            s = fmaf(x, x, s);
        }
        kin[j] = 1.f / fmaxf(sqrtf(s), 1e-12f);
    }
    __syncthreads();

    float* sattn = scratch;
    const float tscale = __ldg(&tempr[head]);

    {
        const int ti = t >> 4;
        const int tj = t & 15;
        const int i0 = ti * 3, j0 = tj * 3;
        float acc[3][3];
        #pragma unroll
        for (int r = 0; r < 3; r++)
            #pragma unroll
            for (int s = 0; s < 3; s++) acc[r][s] = 0.f;

        for (int d0 = 0; d0 < 64; d0 += 4) {
            float4 qv[3];
            #pragma unroll
            for (int r = 0; r < 3; r++)
                qv[r] = *(const float4*)&sq[(i0 + r) * 64 + d0];
            #pragma unroll
            for (int dd = 0; dd < 4; dd++) {
                float kv[3];
                #pragma unroll
                for (int s = 0; s < 3; s++) kv[s] = skT[(d0 + dd) * 52 + j0 + s];
                #pragma unroll
                for (int r = 0; r < 3; r++) {
                    float qd = (dd == 0) ? qv[r].x : (dd == 1) ? qv[r].y
                             : (dd == 2) ? qv[r].z : qv[r].w;
                    #pragma unroll
                    for (int s = 0; s < 3; s++)
                        acc[r][s] = fmaf(qd, kv[s], acc[r][s]);
                }
            }
        }
        #pragma unroll
        for (int r = 0; r < 3; r++) {
            float qi = qin[i0 + r] * tscale;
            #pragma unroll
            for (int s = 0; s < 3; s++)
                sattn[(i0 + r) * 49 + j0 + s] = acc[r][s] * qi * kin[j0 + s];
        }
    }
    __syncthreads();

    if (t < 48) {
        float m = -1e30f;
        #pragma unroll 8
        for (int j = 0; j < 48; j++) m = fmaxf(m, sattn[t * 49 + j]);
        float s = 0.f;
        #pragma unroll 8
        for (int j = 0; j < 48; j++) {
            float e = __expf(sattn[t * 49 + j] - m);
            sattn[t * 49 + j] = e;
            s += e;
        }
        float inv = 1.f / s;
        #pragma unroll 8
        for (int j = 0; j < 48; j++) sattn[t * 49 + j] *= inv;
    }
    __syncthreads();

    // ---- out = attn @ v ; stage as packed bf16 (hi|lo) into skT (u32) ----
    uint32_t* stg = (uint32_t*)skT;                // [64 pix][52 ch]
    {
        const int td = t & 15;            // d0 = 4*td (pixel)
        const int ti = t >> 4;            // i0 = 3*ti (channel)
        const int d0 = td * 4, i0 = ti * 3;
        float acc[3][4];
        #pragma unroll
        for (int r = 0; r < 3; r++)
            #pragma unroll
            for (int s = 0; s < 4; s++) acc[r][s] = 0.f;

        for (int j = 0; j < 48; j++) {
            float4 vv = *(const float4*)&sv[j * 64 + d0];
            #pragma unroll
            for (int r = 0; r < 3; r++) {
                float a = sattn[(i0 + r) * 49 + j];
                acc[r][0] = fmaf(a, vv.x, acc[r][0]);
                acc[r][1] = fmaf(a, vv.y, acc[r][1]);
                acc[r][2] = fmaf(a, vv.z, acc[r][2]);
                acc[r][3] = fmaf(a, vv.w, acc[r][3]);
            }
        }
        __syncthreads();                           // skT reads (norms/logits) done
        #pragma unroll
        for (int r = 0; r < 3; r++)
            #pragma unroll
            for (int s = 0; s < 4; s++) {
                float v = acc[r][s];
                __nv_bfloat16 h = __float2bfloat16(v);
                __nv_bfloat16 l = __float2bfloat16(v - __bfloat162float(h));
                stg[(d0 + s) * 52 + i0 + r] =
                    (uint32_t)*(unsigned short*)&h
                    | ((uint32_t)*(unsigned short*)&l << 16);
            }
    }
    __syncthreads();

    // cooperative transposed writeout: [pix][ch] -> g_bth/g_btl [b][pix][192]
    // 64 rows x 24 ch-pairs = 1536 items, 6 per thread, ushort2 stores
    #pragma unroll
    for (int i = 0; i < 6; i++) {
        int id = t + i * 256;
        int row = id / 24, cp = id - row * 24;
        int c = cp * 2;
        uint32_t w0 = stg[row * 52 + c];
        uint32_t w1 = stg[row * 52 + c + 1];
        int p1 = row >> 3, p2 = row & 7;
        size_t o = ((size_t)b * NPIX + (size_t)(y0 + p1) * 256 + (x0 + p2)) * GK
                 + head * 48 + c;
        *(ushort2*)&g_bth[o] = make_ushort2((unsigned short)w0, (unsigned short)w1);
        *(ushort2*)&g_btl[o] = make_ushort2((unsigned short)(w0 >> 16),
                                            (unsigned short)(w1 >> 16));
    }
}

// ---------------------------------------------------------------------------
extern "C" void kernel_launch(void* const* d_in, const int* in_sizes, int n_in,
                              void* d_out, int out_size)
{
    const float *x = nullptr, *qw = nullptr, *dw = nullptr, *pw = nullptr, *tp = nullptr;
    for (int i = 0; i < n_in; i++) {
        switch (in_sizes[i]) {
            case 25165824: x  = (const float*)d_in[i]; break;  // x [2,192,256,256]
            case 110592:   qw = (const float*)d_in[i]; break;  // qkv_w [576,192]
            case 5184:     dw = (const float*)d_in[i]; break;  // dw_w [576,1,3,3]
            case 36864:    pw = (const float*)d_in[i]; break;  // proj_w [192,192]
            case 4:        tp = (const float*)d_in[i]; break;  // temperature [4]
        }
    }

    void *qkvp, *bthp, *btlp, *wqhp, *wqlp, *wphp, *wplp;
    cudaGetSymbolAddress(&qkvp, g_qkv);
    cudaGetSymbolAddress(&bthp, g_bth);
    cudaGetSymbolAddress(&btlp, g_btl);
    cudaGetSymbolAddress(&wqhp, g_wqh);
    cudaGetSymbolAddress(&wqlp, g_wql);
    cudaGetSymbolAddress(&wphp, g_wph);
    cudaGetSymbolAddress(&wplp, g_wpl);

    const int GEMM_SMEM = 2 * 43008;             // 86016 B
    cudaFuncSetAttribute(gemm_mma, cudaFuncAttributeMaxDynamicSharedMemorySize, GEMM_SMEM);

    wconvert<<<(110592 + 255) / 256, 256>>>(qw, 110592,
        (unsigned short*)wqhp, (unsigned short*)wqlp);
    wconvert<<<(36864 + 255) / 256, 256>>>(pw, 36864,
        (unsigned short*)wphp, (unsigned short*)wplp);

    // 1) x -> x^T bf16 hi/lo
    convtrans<<<dim3(2048, 6, 2), 256>>>(x,
        (unsigned short*)bthp, (unsigned short*)btlp);

    // 2) qkv GEMM (mma.sync): [576,192] x [65536,192]^T
    gemm_mma<<<dim3(9, 512, 2), 256, GEMM_SMEM>>>(
        (const unsigned short*)wqhp, (const unsigned short*)wqlp,
        (const unsigned short*)bthp, (const unsigned short*)btlp,
        (float*)qkvp, 576);

    // 3) fused depthwise 3x3 + attention; writes bf16 hi/lo transposed
    //    (overwrites g_bth/g_btl — safe: qkv GEMM already consumed them)
    window_attn<<<8192, 256>>>(dw, tp);

    // 4) proj GEMM -> d_out
    gemm_mma<<<dim3(3, 512, 2), 256, GEMM_SMEM>>>(
        (const unsigned short*)wphp, (const unsigned short*)wplp,
        (const unsigned short*)bthp, (const unsigned short*)btlp,
        (float*)d_out, 192);
}